// round 8
// baseline (speedup 1.0000x reference)
#include <cuda_runtime.h>

#define N_NODES 20000
#define F_DIM   4
#define T_DIM   12
#define C_DIM   256
#define FT      48          // F*T
#define ER_E    30000
#define HID_D   128
#define OUT_D   12
#define NREG    5

// ---------------- device scratch (no allocations; all zero-initialized at load) ----
// Self-cleaning invariant: every accumulator that a call dirties is re-zeroed by
// that same call (after its last read), so every kernel_launch sees zeros.
__device__ float g_degacc[NREG * N_NODES];   // weighted in-degree accum (zeroed by k_dinv_precomp)
__device__ float g_dinv[NREG * N_NODES];     // rsqrt(deg), fully overwritten each call
__device__ float g_selfc[N_NODES];           // sum_r 1/deg_r, fully overwritten
__device__ float g_Xp[N_NODES * FT];         // x permuted to [n][t*4+f], fully overwritten
__device__ float g_AX[N_NODES * FT];         // edge-aggregated x (zeroed by k_gate after use)
__device__ float g_Mzh[F_DIM * C_DIM * 2];   // folded weights (zeroed by k_mlp)
__device__ float g_bzh[C_DIM * 2];           // folded biases  (zeroed by k_mlp)
__device__ float g_probs[T_DIM];             // softmax(attention), fully overwritten
__device__ float g_hreluT[C_DIM * N_NODES];  // relu(h), TRANSPOSED [c][n], fully overwritten

struct RegPtrs { const int* idx[NREG]; const float* w[NREG]; };

// ---------------- 1: permute x AND accumulate weighted in-degree ----------------
__global__ void k_deg_perm(const float* __restrict__ x, RegPtrs rp) {
    int i = blockIdx.x * blockDim.x + threadIdx.x;
    if (i < N_NODES * FT) {
        int n = i / FT;
        int e = i - n * FT;          // e = f*12 + t
        int f = e / T_DIM;
        int t = e - f * T_DIM;
        g_Xp[n * FT + t * 4 + f] = x[i];
    }
    if (i < NREG * ER_E) {
        int r = i / ER_E;
        int e = i - r * ER_E;
        int dst = rp.idx[r][ER_E + e];
        atomicAdd(&g_degacc[r * N_NODES + dst], rp.w[r][e]);
    }
}

// ---------------- 2: fused dinv (blocks 0..78) + weight-fold (blocks 79..94) ------
#define DINV_BLOCKS 79
__global__ void k_dinv_precomp(const float* __restrict__ Wc_z, const float* __restrict__ bc_z,
                               const float* __restrict__ Wl_z, const float* __restrict__ bl_z,
                               const float* __restrict__ Wc_h, const float* __restrict__ bc_h,
                               const float* __restrict__ Wl_h, const float* __restrict__ bl_h,
                               const float* __restrict__ attention) {
    int tid = threadIdx.x;
    if (blockIdx.x < DINV_BLOCKS) {
        int i = blockIdx.x * 256 + tid;
        if (i < N_NODES) {
            float s = 0.f;
#pragma unroll
            for (int r = 0; r < NREG; r++) {
                float d = g_degacc[r * N_NODES + i] + 1.0f;   // +1 self-loop
                g_degacc[r * N_NODES + i] = 0.f;              // clean for next call
                g_dinv[r * N_NODES + i] = rsqrtf(d);
                s += __fdividef(1.0f, d);
            }
            g_selfc[i] = s;
        }
        return;
    }
    // ---- weight fold: M = Wc@Wl[:C], b' = bc@Wl[:C] + bl; 16 blocks, k-slice each ----
    __shared__ float sWcz[F_DIM * 16], sWch[F_DIM * 16];
    __shared__ float sbcz[16], sbch[16];
    int b = blockIdx.x - DINV_BLOCKS;   // 0..15
    int k0 = b * 16;
    if (tid < F_DIM * 16) {
        int f = tid >> 4, kk = tid & 15;
        sWcz[tid] = Wc_z[f * C_DIM + k0 + kk];
        sWch[tid] = Wc_h[f * C_DIM + k0 + kk];
    }
    if (tid < 16) { sbcz[tid] = bc_z[k0 + tid]; sbch[tid] = bc_h[k0 + tid]; }
    __syncthreads();
    float mz[F_DIM] = {0, 0, 0, 0}, mh[F_DIM] = {0, 0, 0, 0}, bz = 0.f, bh = 0.f;
#pragma unroll 4
    for (int kk = 0; kk < 16; kk++) {
        int k = k0 + kk;
        float wz = Wl_z[k * C_DIM + tid];
        float wh = Wl_h[k * C_DIM + tid];
#pragma unroll
        for (int f = 0; f < F_DIM; f++) {
            mz[f] = fmaf(sWcz[f * 16 + kk], wz, mz[f]);
            mh[f] = fmaf(sWch[f * 16 + kk], wh, mh[f]);
        }
        bz = fmaf(sbcz[kk], wz, bz);
        bh = fmaf(sbch[kk], wh, bh);
    }
#pragma unroll
    for (int f = 0; f < F_DIM; f++) {
        atomicAdd(&g_Mzh[(f * C_DIM + tid) * 2],     mz[f]);
        atomicAdd(&g_Mzh[(f * C_DIM + tid) * 2 + 1], mh[f]);
    }
    if (b == 0) { bz += bl_z[tid]; bh += bl_h[tid]; }
    atomicAdd(&g_bzh[tid * 2],     bz);
    atomicAdd(&g_bzh[tid * 2 + 1], bh);
    if (b == 0 && tid == 0) {
        float mx = -1e30f;
        for (int t = 0; t < T_DIM; t++) mx = fmaxf(mx, attention[t]);
        float p[T_DIM], s = 0.f;
        for (int t = 0; t < T_DIM; t++) { p[t] = __expf(attention[t] - mx); s += p[t]; }
        float is = __fdividef(1.0f, s);
        for (int t = 0; t < T_DIM; t++) g_probs[t] = p[t] * is;
    }
}

// ---------------- 3: edge scatter with v4 reductions ----------------
// 4 lanes per edge; each lane does 3 x red.global.add.v4.f32 (48 floats/edge)
__global__ void k_scatter(RegPtrs rp) {
    int lane = threadIdx.x & 31;
    int warp = threadIdx.x >> 5;                       // 0..7
    int r = blockIdx.y;
    int e = (blockIdx.x * 8 + warp) * 8 + (lane >> 2);
    int part = lane & 3;
    if (e >= ER_E) return;
    const int* idx = rp.idx[r];
    int src = idx[e];
    int dst = idx[ER_E + e];
    float coef = g_dinv[r * N_NODES + src] * rp.w[r][e] * g_dinv[r * N_NODES + dst];
    const float4* xs = (const float4*)(g_Xp + (size_t)src * FT) + part * 3;
    float4* ax = (float4*)(g_AX + (size_t)dst * FT) + part * 3;
#pragma unroll
    for (int q = 0; q < 3; q++) {
        float4 v = xs[q];
        asm volatile("red.global.add.v4.f32 [%0], {%1, %2, %3, %4};"
                     :: "l"(ax + q), "f"(coef * v.x), "f"(coef * v.y),
                        "f"(coef * v.z), "f"(coef * v.w) : "memory");
    }
}

// ---------------- 4 (PROFILED SLOT): gate kernel ----------------
// smem floats: Mzh 2048 | bzh 512 | AXd 3072 (duplicated pairs) | hs 32*257=8224
#define GATE_NPB   32
#define GATE_SMEMF (2048 + 512 + 3072 + 32 * 257)
#define GATE_SMEMB (GATE_SMEMF * 4)

__global__ void __launch_bounds__(256, 4)
k_gate(float* __restrict__ out_h, int write_h) {
    extern __shared__ float sm[];
    float* Mzs = sm;                 // 2048 (interleaved mz,mh)
    float* bzs = Mzs + 2048;         // 512
    float* AXd = bzs + 512;          // 3072: [n][t*4+f], each value duplicated
    float* hs  = AXd + 3072;         // 32 * 257 (padded for transpose)

    int tid = threadIdx.x;
    for (int i = tid; i < 2048; i += 256) Mzs[i] = g_Mzh[i];
    bzs[tid] = g_bzh[tid];
    bzs[256 + tid] = g_bzh[256 + tid];
    int base = blockIdx.x * GATE_NPB;
    // fused self-loop: AX_total = AX_edges + selfc[n] * Xp ; then clean AX for next call
    for (int i = tid; i < GATE_NPB * FT; i += 256) {
        int n = base + i / FT;
        float v = fmaf(g_selfc[n], g_Xp[base * FT + i], g_AX[base * FT + i]);
        g_AX[base * FT + i] = 0.f;                    // self-cleaning accumulator
        ((float2*)AXd)[i] = make_float2(v, v);
    }
    __syncthreads();

    float pr[T_DIM];
#pragma unroll
    for (int t = 0; t < T_DIM; t++) pr[t] = g_probs[t];

    int c = tid;
    const unsigned long long* M64 = (const unsigned long long*)Mzs;
    unsigned long long mm0 = M64[c], mm1 = M64[256 + c], mm2 = M64[512 + c], mm3 = M64[768 + c];
    unsigned long long bb = ((const unsigned long long*)bzs)[c];

    for (int ln = 0; ln < GATE_NPB; ln++) {
        const ulonglong2* axp = (const ulonglong2*)(AXd + ln * 96);
        float Nacc = 0.f, Dacc = 1.f;
#pragma unroll
        for (int t = 0; t < T_DIM; t++) {
            ulonglong2 a01 = axp[2 * t];
            ulonglong2 a23 = axp[2 * t + 1];
            unsigned long long d = bb;
            asm("fma.rn.f32x2 %0, %1, %2, %0;" : "+l"(d) : "l"(a01.x), "l"(mm0));
            asm("fma.rn.f32x2 %0, %1, %2, %0;" : "+l"(d) : "l"(a01.y), "l"(mm1));
            asm("fma.rn.f32x2 %0, %1, %2, %0;" : "+l"(d) : "l"(a23.x), "l"(mm2));
            asm("fma.rn.f32x2 %0, %1, %2, %0;" : "+l"(d) : "l"(a23.y), "l"(mm3));
            float az, ah;
            asm("mov.b64 {%0, %1}, %2;" : "=f"(az), "=f"(ah) : "l"(d));
            // stable form, denominators in [1,4]:
            //   (1-sigmoid(az)) = (az>=0 ? em : 1)/(1+em),    em  = e^{-|az|}
            //   tanh(ah)        = copysign(1-em2, ah)/(1+em2), em2 = e^{-2|ah|}
            float em  = __expf(-fabsf(az));
            float em2 = __expf(-2.0f * fabsf(ah));
            float ns  = (az >= 0.f) ? em : 1.0f;
            float n_t = ns * copysignf(1.0f - em2, ah) * pr[t];
            float d_t = (1.0f + em) * (1.0f + em2);
            // running fraction: N/D = sum_{<=t} n/d ;  D <= 4^12, never overflows
            Nacc = fmaf(Nacc, d_t, n_t * Dacc);
            Dacc *= d_t;
        }
        float acc = __fdividef(Nacc, Dacc);          // ONE division per (node,channel)
        if (write_h) out_h[(base + ln) * C_DIM + c] = acc;   // raw h output
        hs[ln * 257 + c] = fmaxf(acc, 0.f);
    }
    __syncthreads();

    // transposed relu'd write: g_hreluT[c][n]
    for (int idx = tid; idx < GATE_NPB * C_DIM; idx += 256) {
        int cc = idx >> 5, n = idx & 31;
        g_hreluT[cc * N_NODES + base + n] = hs[n * 257 + cc];
    }
}

// ---------------- 5: MLP kernel: relu(h) @ W1 -> relu -> @ W2 ----------------
// smem floats: hTs 16384 (reused as y1s) | b1 128 | b2 16 | W2 1536 = 18064
#define MLP_NPB   64
#define MLP_SMEMF (16384 + 128 + 16 + 1536)
#define MLP_SMEMB (MLP_SMEMF * 4)

__global__ void __launch_bounds__(256, 3)
k_mlp(const float* __restrict__ W1, const float* __restrict__ b1,
      const float* __restrict__ W2, const float* __restrict__ b2,
      float* __restrict__ out_y) {
    extern __shared__ float sm[];
    float* hTs = sm;                  // 16384  [k][n]  (aliased to y1s after sync)
    float* b1s = hTs + 16384;         // 128
    float* b2s = b1s + 128;           // 16
    float* W2s = b2s + 16;            // 1536

    int tid = threadIdx.x;
    int base = blockIdx.x * MLP_NPB;

    // block 0 also cleans the folded-weight accumulators for the next call
    if (blockIdx.x == 0) {
        for (int i = tid; i < F_DIM * C_DIM * 2; i += 256) g_Mzh[i] = 0.f;
        g_bzh[tid] = 0.f;
        g_bzh[256 + tid] = 0.f;
    }

    for (int i = tid; i < 1536; i += 256) W2s[i] = W2[i];
    if (tid < HID_D) b1s[tid] = b1[tid];
    if (tid < 16) b2s[tid] = (tid < OUT_D) ? b2[tid] : 0.f;
    for (int i = tid; i < C_DIM * MLP_NPB; i += 256) {
        int k = i >> 6, n = i & 63;
        int gn = base + n;
        hTs[i] = (gn < N_NODES) ? g_hreluT[k * N_NODES + gn] : 0.f;
    }
    __syncthreads();

    // layer 1, packed-fp32 pipe: thread (j, half) covers 32 nodes = 16 f32x2 pairs
    int j = tid & 127;
    int half = tid >> 7;
    unsigned long long acc[16];
    {
        float bj = b1s[j];
        unsigned long long binit;
        asm("mov.b64 %0, {%1, %1};" : "=l"(binit) : "f"(bj));
#pragma unroll
        for (int p = 0; p < 16; p++) acc[p] = binit;
    }
    const float* hbase = hTs + half * 32;
#pragma unroll 1
    for (int k0 = 0; k0 < C_DIM; k0 += 8) {
        float wreg[8];                               // 8-wide prefetch
#pragma unroll
        for (int kk = 0; kk < 8; kk++) wreg[kk] = W1[(k0 + kk) * HID_D + j];
#pragma unroll
        for (int kk = 0; kk < 8; kk++) {
            unsigned long long w2;
            asm("mov.b64 %0, {%1, %1};" : "=l"(w2) : "f"(wreg[kk]));
            const ulonglong2* hp = (const ulonglong2*)(hbase + (k0 + kk) * MLP_NPB);
#pragma unroll
            for (int q = 0; q < 8; q++) {
                ulonglong2 hv = hp[q];
                asm("fma.rn.f32x2 %0, %1, %2, %0;" : "+l"(acc[2 * q])     : "l"(hv.x), "l"(w2));
                asm("fma.rn.f32x2 %0, %1, %2, %0;" : "+l"(acc[2 * q + 1]) : "l"(hv.y), "l"(w2));
            }
        }
    }
    __syncthreads();          // everyone done reading hTs
    float* y1s = hTs;         // reuse as [n][j]
#pragma unroll
    for (int p = 0; p < 16; p++) {
        float lo, hi;
        asm("mov.b64 {%0, %1}, %2;" : "=f"(lo), "=f"(hi) : "l"(acc[p]));
        int n0 = half * 32 + 2 * p;
        y1s[n0 * HID_D + j]       = fmaxf(lo, 0.f);
        y1s[(n0 + 1) * HID_D + j] = fmaxf(hi, 0.f);
    }
    __syncthreads();

    // layer 2: 64 nodes x 12 outputs
    for (int o = tid; o < MLP_NPB * OUT_D; o += 256) {
        int n = o / OUT_D, oo = o - n * OUT_D;
        int gn = base + n;
        if (gn < N_NODES) {
            float s = b2s[oo];
            const float* yr = y1s + n * HID_D;
#pragma unroll 16
            for (int jj = 0; jj < HID_D; jj++) s = fmaf(yr[jj], W2s[jj * OUT_D + oo], s);
            out_y[gn * OUT_D + oo] = s;
        }
    }
}

// ---------------- launch ----------------
extern "C" void kernel_launch(void* const* d_in, const int* in_sizes, int n_in,
                              void* d_out, int out_size) {
    (void)in_sizes; (void)n_in;
    const float* x = (const float*)d_in[0];
    // d_in[1] = full-graph edge_index: provably unused by the reference
    RegPtrs rp;
    for (int r = 0; r < NREG; r++) {
        rp.idx[r] = (const int*)d_in[2 + r];
        rp.w[r]   = (const float*)d_in[7 + r];
    }
    const float* Wc_z = (const float*)d_in[12];
    const float* bc_z = (const float*)d_in[13];
    const float* Wl_z = (const float*)d_in[14];
    const float* bl_z = (const float*)d_in[15];
    // d_in[16..19] = reset-gate params: cannot influence output (H0 = 0)
    const float* Wc_h = (const float*)d_in[20];
    const float* bc_h = (const float*)d_in[21];
    const float* Wl_h = (const float*)d_in[22];
    const float* bl_h = (const float*)d_in[23];
    const float* att  = (const float*)d_in[24];
    const float* W1   = (const float*)d_in[25];
    const float* b1   = (const float*)d_in[26];
    const float* W2   = (const float*)d_in[27];
    const float* b2   = (const float*)d_in[28];

    float* out   = (float*)d_out;
    float* out_y = out;
    int write_h  = (out_size >= N_NODES * (OUT_D + C_DIM)) ? 1 : 0;
    float* out_h = out + N_NODES * OUT_D;

    k_deg_perm<<<(N_NODES * FT + 255) / 256, 256>>>(x, rp);              // 1
    k_dinv_precomp<<<DINV_BLOCKS + 16, 256>>>(Wc_z, bc_z, Wl_z, bl_z,
                                              Wc_h, bc_h, Wl_h, bl_h, att); // 2
    dim3 gsc((ER_E + 63) / 64, NREG);   // 64 edges/block, 4 lanes/edge
    k_scatter<<<gsc, 256>>>(rp);                                         // 3

    cudaFuncSetAttribute(k_gate, cudaFuncAttributeMaxDynamicSharedMemorySize, GATE_SMEMB);
    k_gate<<<N_NODES / GATE_NPB, 256, GATE_SMEMB>>>(out_h, write_h);     // 4 <- profiled

    cudaFuncSetAttribute(k_mlp, cudaFuncAttributeMaxDynamicSharedMemorySize, MLP_SMEMB);
    k_mlp<<<(N_NODES + MLP_NPB - 1) / MLP_NPB, 256, MLP_SMEMB>>>(W1, b1, W2, b2, out_y); // 5
}

// round 10
// speedup vs baseline: 1.1787x; 1.1787x over previous
#include <cuda_runtime.h>

#define N_NODES 20000
#define F_DIM   4
#define T_DIM   12
#define C_DIM   256
#define FT      48          // F*T
#define ER_E    30000
#define HID_D   128
#define OUT_D   12
#define NREG    5

// ---------------- device scratch (no allocations; all zero-initialized at load) ----
// Self-cleaning invariant: every accumulator a call dirties is re-zeroed by that
// same call after its last read, so every kernel_launch sees zeros.
__device__ float g_degacc[NREG * N_NODES];   // weighted in-degree accum (zeroed by k_dinv_precomp)
__device__ float g_dinv[NREG * N_NODES];     // rsqrt(deg), fully overwritten each call
__device__ float g_selfc[N_NODES];           // sum_r 1/deg_r, fully overwritten
__device__ float g_Xp[N_NODES * FT];         // x permuted to [n][t*4+f], fully overwritten
__device__ float g_AX[N_NODES * FT];         // edge-aggregated x (zeroed by k_gate after use)
__device__ float g_Mzh[F_DIM * C_DIM * 2];   // folded weights, z-half pre-scaled by 0.5 (zeroed by k_mlp)
__device__ float g_bzh[C_DIM * 2];           // folded biases,  z-half pre-scaled by 0.5 (zeroed by k_mlp)
__device__ float g_probs[T_DIM];             // 0.5 * softmax(attention), fully overwritten
__device__ float g_hreluT[C_DIM * N_NODES];  // relu(h), TRANSPOSED [c][n], fully overwritten

struct RegPtrs { const int* idx[NREG]; const float* w[NREG]; };

// ---------------- 1: permute x AND accumulate weighted in-degree ----------------
__global__ void k_deg_perm(const float* __restrict__ x, RegPtrs rp) {
    int i = blockIdx.x * blockDim.x + threadIdx.x;
    if (i < N_NODES * FT) {
        int n = i / FT;
        int e = i - n * FT;          // e = f*12 + t
        int f = e / T_DIM;
        int t = e - f * T_DIM;
        g_Xp[n * FT + t * 4 + f] = x[i];
    }
    if (i < NREG * ER_E) {
        int r = i / ER_E;
        int e = i - r * ER_E;
        int dst = rp.idx[r][ER_E + e];
        atomicAdd(&g_degacc[r * N_NODES + dst], rp.w[r][e]);
    }
}

// ---------------- 2: fused dinv (blocks 0..78) + weight-fold (blocks 79..94) ------
// Fold: M = Wc@Wl[:C], b' = bc@Wl[:C] + bl.  The z-gate halves are additionally
// scaled by 0.5 so the gate can use (1-sigmoid(az)) = 0.5*(1 - tanh(az/2)).
#define DINV_BLOCKS 79
__global__ void k_dinv_precomp(const float* __restrict__ Wc_z, const float* __restrict__ bc_z,
                               const float* __restrict__ Wl_z, const float* __restrict__ bl_z,
                               const float* __restrict__ Wc_h, const float* __restrict__ bc_h,
                               const float* __restrict__ Wl_h, const float* __restrict__ bl_h,
                               const float* __restrict__ attention) {
    int tid = threadIdx.x;
    if (blockIdx.x < DINV_BLOCKS) {
        int i = blockIdx.x * 256 + tid;
        if (i < N_NODES) {
            float s = 0.f;
#pragma unroll
            for (int r = 0; r < NREG; r++) {
                float d = g_degacc[r * N_NODES + i] + 1.0f;   // +1 self-loop
                g_degacc[r * N_NODES + i] = 0.f;              // clean for next call
                g_dinv[r * N_NODES + i] = rsqrtf(d);
                s += __fdividef(1.0f, d);
            }
            g_selfc[i] = s;
        }
        return;
    }
    __shared__ float sWcz[F_DIM * 16], sWch[F_DIM * 16];
    __shared__ float sbcz[16], sbch[16];
    int b = blockIdx.x - DINV_BLOCKS;   // 0..15
    int k0 = b * 16;
    if (tid < F_DIM * 16) {
        int f = tid >> 4, kk = tid & 15;
        sWcz[tid] = Wc_z[f * C_DIM + k0 + kk];
        sWch[tid] = Wc_h[f * C_DIM + k0 + kk];
    }
    if (tid < 16) { sbcz[tid] = bc_z[k0 + tid]; sbch[tid] = bc_h[k0 + tid]; }
    __syncthreads();
    float mz[F_DIM] = {0, 0, 0, 0}, mh[F_DIM] = {0, 0, 0, 0}, bz = 0.f, bh = 0.f;
#pragma unroll 4
    for (int kk = 0; kk < 16; kk++) {
        int k = k0 + kk;
        float wz = Wl_z[k * C_DIM + tid];
        float wh = Wl_h[k * C_DIM + tid];
#pragma unroll
        for (int f = 0; f < F_DIM; f++) {
            mz[f] = fmaf(sWcz[f * 16 + kk], wz, mz[f]);
            mh[f] = fmaf(sWch[f * 16 + kk], wh, mh[f]);
        }
        bz = fmaf(sbcz[kk], wz, bz);
        bh = fmaf(sbch[kk], wh, bh);
    }
#pragma unroll
    for (int f = 0; f < F_DIM; f++) {
        atomicAdd(&g_Mzh[(f * C_DIM + tid) * 2],     0.5f * mz[f]);  // z-half carries the /2
        atomicAdd(&g_Mzh[(f * C_DIM + tid) * 2 + 1], mh[f]);
    }
    if (b == 0) { bz += bl_z[tid]; bh += bl_h[tid]; }
    atomicAdd(&g_bzh[tid * 2],     0.5f * bz);                        // z-half carries the /2
    atomicAdd(&g_bzh[tid * 2 + 1], bh);
    if (b == 0 && tid == 0) {
        float mx = -1e30f;
        for (int t = 0; t < T_DIM; t++) mx = fmaxf(mx, attention[t]);
        float p[T_DIM], s = 0.f;
        for (int t = 0; t < T_DIM; t++) { p[t] = __expf(attention[t] - mx); s += p[t]; }
        float is = __fdividef(0.5f, s);                               // 0.5 * softmax folded here
        for (int t = 0; t < T_DIM; t++) g_probs[t] = p[t] * is;
    }
}

// ---------------- 3: edge scatter with v4 reductions ----------------
// 4 lanes per edge; each lane does 3 x red.global.add.v4.f32 (48 floats/edge)
__global__ void k_scatter(RegPtrs rp) {
    int lane = threadIdx.x & 31;
    int warp = threadIdx.x >> 5;                       // 0..7
    int r = blockIdx.y;
    int e = (blockIdx.x * 8 + warp) * 8 + (lane >> 2);
    int part = lane & 3;
    if (e >= ER_E) return;
    const int* idx = rp.idx[r];
    int src = idx[e];
    int dst = idx[ER_E + e];
    float coef = g_dinv[r * N_NODES + src] * rp.w[r][e] * g_dinv[r * N_NODES + dst];
    const float4* xs = (const float4*)(g_Xp + (size_t)src * FT) + part * 3;
    float4* ax = (float4*)(g_AX + (size_t)dst * FT) + part * 3;
#pragma unroll
    for (int q = 0; q < 3; q++) {
        float4 v = xs[q];
        asm volatile("red.global.add.v4.f32 [%0], {%1, %2, %3, %4};"
                     :: "l"(ax + q), "f"(coef * v.x), "f"(coef * v.y),
                        "f"(coef * v.z), "f"(coef * v.w) : "memory");
    }
}

// ---------------- 4 (PROFILED SLOT): gate kernel, MUFU.TANH form ----------------
// h = sum_t p_t * (1-sigmoid(az)) * tanh(ah)
//   = sum_t (0.5*p_t) * (1 - tanh(az'/1)) * tanh(ah),   az' already = az/2 via fold
// smem floats: Mzh 2048 | bzh 512 | AXd 3072 (duplicated pairs) | hs 32*257=8224
#define GATE_NPB   32
#define GATE_SMEMF (2048 + 512 + 3072 + 32 * 257)
#define GATE_SMEMB (GATE_SMEMF * 4)

__global__ void __launch_bounds__(256, 4)
k_gate(float* __restrict__ out_h, int write_h) {
    extern __shared__ float sm[];
    float* Mzs = sm;                 // 2048 (interleaved mz', mh)
    float* bzs = Mzs + 2048;         // 512
    float* AXd = bzs + 512;          // 3072: [n][t*4+f], each value duplicated
    float* hs  = AXd + 3072;         // 32 * 257 (padded for transpose)

    int tid = threadIdx.x;
    for (int i = tid; i < 2048; i += 256) Mzs[i] = g_Mzh[i];
    bzs[tid] = g_bzh[tid];
    bzs[256 + tid] = g_bzh[256 + tid];
    int base = blockIdx.x * GATE_NPB;
    // fused self-loop: AX_total = AX_edges + selfc[n] * Xp ; then clean AX for next call
    for (int i = tid; i < GATE_NPB * FT; i += 256) {
        int n = base + i / FT;
        float v = fmaf(g_selfc[n], g_Xp[base * FT + i], g_AX[base * FT + i]);
        g_AX[base * FT + i] = 0.f;                    // self-cleaning accumulator
        ((float2*)AXd)[i] = make_float2(v, v);
    }
    __syncthreads();

    float pr2[T_DIM];                                 // 0.5 * softmax (folded)
#pragma unroll
    for (int t = 0; t < T_DIM; t++) pr2[t] = g_probs[t];

    int c = tid;
    const unsigned long long* M64 = (const unsigned long long*)Mzs;
    unsigned long long mm0 = M64[c], mm1 = M64[256 + c], mm2 = M64[512 + c], mm3 = M64[768 + c];
    unsigned long long bb = ((const unsigned long long*)bzs)[c];

    for (int ln = 0; ln < GATE_NPB; ln++) {
        const ulonglong2* axp = (const ulonglong2*)(AXd + ln * 96);
        float acc = 0.f;
#pragma unroll
        for (int t = 0; t < T_DIM; t++) {
            ulonglong2 a01 = axp[2 * t];
            ulonglong2 a23 = axp[2 * t + 1];
            unsigned long long d = bb;
            asm("fma.rn.f32x2 %0, %1, %2, %0;" : "+l"(d) : "l"(a01.x), "l"(mm0));
            asm("fma.rn.f32x2 %0, %1, %2, %0;" : "+l"(d) : "l"(a01.y), "l"(mm1));
            asm("fma.rn.f32x2 %0, %1, %2, %0;" : "+l"(d) : "l"(a23.x), "l"(mm2));
            asm("fma.rn.f32x2 %0, %1, %2, %0;" : "+l"(d) : "l"(a23.y), "l"(mm3));
            float azh, ah;                            // azh = az/2 (fold), ah = raw
            asm("mov.b64 {%0, %1}, %2;" : "=f"(azh), "=f"(ah) : "l"(d));
            float t1, t2;
            asm("tanh.approx.f32 %0, %1;" : "=f"(t1) : "f"(azh));
            asm("tanh.approx.f32 %0, %1;" : "=f"(t2) : "f"(ah));
            acc = fmaf(pr2[t] * (1.0f - t1), t2, acc);
        }
        if (write_h) out_h[(base + ln) * C_DIM + c] = acc;   // raw h output
        hs[ln * 257 + c] = fmaxf(acc, 0.f);
    }
    __syncthreads();

    // transposed relu'd write: g_hreluT[c][n]
    for (int idx = tid; idx < GATE_NPB * C_DIM; idx += 256) {
        int cc = idx >> 5, n = idx & 31;
        g_hreluT[cc * N_NODES + base + n] = hs[n * 257 + cc];
    }
}

// ---------------- 5: MLP kernel: relu(h) @ W1 -> relu -> @ W2 ----------------
// smem floats: hTs 16384 (reused as y1s) | b1 128 | b2 16 | W2 1536 = 18064
#define MLP_NPB   64
#define MLP_SMEMF (16384 + 128 + 16 + 1536)
#define MLP_SMEMB (MLP_SMEMF * 4)

__global__ void __launch_bounds__(256, 3)
k_mlp(const float* __restrict__ W1, const float* __restrict__ b1,
      const float* __restrict__ W2, const float* __restrict__ b2,
      float* __restrict__ out_y) {
    extern __shared__ float sm[];
    float* hTs = sm;                  // 16384  [k][n]  (aliased to y1s after sync)
    float* b1s = hTs + 16384;         // 128
    float* b2s = b1s + 128;           // 16
    float* W2s = b2s + 16;            // 1536

    int tid = threadIdx.x;
    int base = blockIdx.x * MLP_NPB;

    // block 0 also cleans the folded-weight accumulators for the next call
    if (blockIdx.x == 0) {
        for (int i = tid; i < F_DIM * C_DIM * 2; i += 256) g_Mzh[i] = 0.f;
        g_bzh[tid] = 0.f;
        g_bzh[256 + tid] = 0.f;
    }

    for (int i = tid; i < 1536; i += 256) W2s[i] = W2[i];
    if (tid < HID_D) b1s[tid] = b1[tid];
    if (tid < 16) b2s[tid] = (tid < OUT_D) ? b2[tid] : 0.f;
    for (int i = tid; i < C_DIM * MLP_NPB; i += 256) {
        int k = i >> 6, n = i & 63;
        int gn = base + n;
        hTs[i] = (gn < N_NODES) ? g_hreluT[k * N_NODES + gn] : 0.f;
    }
    __syncthreads();

    // layer 1, packed-fp32 pipe: thread (j, half) covers 32 nodes = 16 f32x2 pairs
    int j = tid & 127;
    int half = tid >> 7;
    unsigned long long acc[16];
    {
        float bj = b1s[j];
        unsigned long long binit;
        asm("mov.b64 %0, {%1, %1};" : "=l"(binit) : "f"(bj));
#pragma unroll
        for (int p = 0; p < 16; p++) acc[p] = binit;
    }
    const float* hbase = hTs + half * 32;
#pragma unroll 1
    for (int k0 = 0; k0 < C_DIM; k0 += 8) {
        float wreg[8];                               // 8-wide prefetch
#pragma unroll
        for (int kk = 0; kk < 8; kk++) wreg[kk] = W1[(k0 + kk) * HID_D + j];
#pragma unroll
        for (int kk = 0; kk < 8; kk++) {
            unsigned long long w2;
            asm("mov.b64 %0, {%1, %1};" : "=l"(w2) : "f"(wreg[kk]));
            const ulonglong2* hp = (const ulonglong2*)(hbase + (k0 + kk) * MLP_NPB);
#pragma unroll
            for (int q = 0; q < 8; q++) {
                ulonglong2 hv = hp[q];
                asm("fma.rn.f32x2 %0, %1, %2, %0;" : "+l"(acc[2 * q])     : "l"(hv.x), "l"(w2));
                asm("fma.rn.f32x2 %0, %1, %2, %0;" : "+l"(acc[2 * q + 1]) : "l"(hv.y), "l"(w2));
            }
        }
    }
    __syncthreads();          // everyone done reading hTs
    float* y1s = hTs;         // reuse as [n][j]
#pragma unroll
    for (int p = 0; p < 16; p++) {
        float lo, hi;
        asm("mov.b64 {%0, %1}, %2;" : "=f"(lo), "=f"(hi) : "l"(acc[p]));
        int n0 = half * 32 + 2 * p;
        y1s[n0 * HID_D + j]       = fmaxf(lo, 0.f);
        y1s[(n0 + 1) * HID_D + j] = fmaxf(hi, 0.f);
    }
    __syncthreads();

    // layer 2: 64 nodes x 12 outputs
    for (int o = tid; o < MLP_NPB * OUT_D; o += 256) {
        int n = o / OUT_D, oo = o - n * OUT_D;
        int gn = base + n;
        if (gn < N_NODES) {
            float s = b2s[oo];
            const float* yr = y1s + n * HID_D;
#pragma unroll 16
            for (int jj = 0; jj < HID_D; jj++) s = fmaf(yr[jj], W2s[jj * OUT_D + oo], s);
            out_y[gn * OUT_D + oo] = s;
        }
    }
}

// ---------------- launch ----------------
extern "C" void kernel_launch(void* const* d_in, const int* in_sizes, int n_in,
                              void* d_out, int out_size) {
    (void)in_sizes; (void)n_in;
    const float* x = (const float*)d_in[0];
    // d_in[1] = full-graph edge_index: provably unused by the reference
    RegPtrs rp;
    for (int r = 0; r < NREG; r++) {
        rp.idx[r] = (const int*)d_in[2 + r];
        rp.w[r]   = (const float*)d_in[7 + r];
    }
    const float* Wc_z = (const float*)d_in[12];
    const float* bc_z = (const float*)d_in[13];
    const float* Wl_z = (const float*)d_in[14];
    const float* bl_z = (const float*)d_in[15];
    // d_in[16..19] = reset-gate params: cannot influence output (H0 = 0)
    const float* Wc_h = (const float*)d_in[20];
    const float* bc_h = (const float*)d_in[21];
    const float* Wl_h = (const float*)d_in[22];
    const float* bl_h = (const float*)d_in[23];
    const float* att  = (const float*)d_in[24];
    const float* W1   = (const float*)d_in[25];
    const float* b1   = (const float*)d_in[26];
    const float* W2   = (const float*)d_in[27];
    const float* b2   = (const float*)d_in[28];

    float* out   = (float*)d_out;
    float* out_y = out;
    int write_h  = (out_size >= N_NODES * (OUT_D + C_DIM)) ? 1 : 0;
    float* out_h = out + N_NODES * OUT_D;

    k_deg_perm<<<(N_NODES * FT + 255) / 256, 256>>>(x, rp);              // 1
    k_dinv_precomp<<<DINV_BLOCKS + 16, 256>>>(Wc_z, bc_z, Wl_z, bl_z,
                                              Wc_h, bc_h, Wl_h, bl_h, att); // 2
    dim3 gsc((ER_E + 63) / 64, NREG);   // 64 edges/block, 4 lanes/edge
    k_scatter<<<gsc, 256>>>(rp);                                         // 3

    cudaFuncSetAttribute(k_gate, cudaFuncAttributeMaxDynamicSharedMemorySize, GATE_SMEMB);
    k_gate<<<N_NODES / GATE_NPB, 256, GATE_SMEMB>>>(out_h, write_h);     // 4 <- profiled

    cudaFuncSetAttribute(k_mlp, cudaFuncAttributeMaxDynamicSharedMemorySize, MLP_SMEMB);
    k_mlp<<<(N_NODES + MLP_NPB - 1) / MLP_NPB, 256, MLP_SMEMB>>>(W1, b1, W2, b2, out_y); // 5
}

// round 11
// speedup vs baseline: 1.2174x; 1.0328x over previous
#include <cuda_runtime.h>

#define N_NODES 20000
#define F_DIM   4
#define T_DIM   12
#define C_DIM   256
#define FT      48          // F*T
#define ER_E    30000
#define HID_D   128
#define OUT_D   12
#define NREG    5

// ---------------- device scratch (no allocations; all zero-initialized at load) ----
// Self-cleaning invariant: every accumulator a call dirties is re-zeroed by that
// same call after its last read, so every kernel_launch sees zeros.
__device__ float g_degacc[NREG * N_NODES];   // weighted in-degree accum (zeroed by k_dinv_precomp)
__device__ float g_dinv[NREG * N_NODES];     // rsqrt(deg), fully overwritten each call
__device__ float g_selfc[N_NODES];           // sum_r 1/deg_r, fully overwritten
__device__ float g_Xp[N_NODES * FT];         // x permuted to [n][t*4+f], fully overwritten
__device__ float g_AX[N_NODES * FT];         // edge-aggregated x (zeroed by k_gate after use)
__device__ float g_Mzh[F_DIM * C_DIM * 2];   // folded weights, z-half pre-scaled by 0.5 (zeroed by k_mlp)
__device__ float g_bzh[C_DIM * 2];           // folded biases,  z-half pre-scaled by 0.5 (zeroed by k_mlp)
__device__ float g_probs[T_DIM];             // 0.5 * softmax(attention), fully overwritten
__device__ float g_hreluT[C_DIM * N_NODES];  // relu(h), TRANSPOSED [c][n], fully overwritten

struct RegPtrs { const int* idx[NREG]; const float* w[NREG]; };

// ---------------- 1: permute x AND accumulate weighted in-degree ----------------
__global__ void k_deg_perm(const float* __restrict__ x, RegPtrs rp) {
    int i = blockIdx.x * blockDim.x + threadIdx.x;
    if (i < N_NODES * FT) {
        int n = i / FT;
        int e = i - n * FT;          // e = f*12 + t
        int f = e / T_DIM;
        int t = e - f * T_DIM;
        g_Xp[n * FT + t * 4 + f] = x[i];
    }
    if (i < NREG * ER_E) {
        int r = i / ER_E;
        int e = i - r * ER_E;
        int dst = rp.idx[r][ER_E + e];
        atomicAdd(&g_degacc[r * N_NODES + dst], rp.w[r][e]);
    }
}

// ---------------- 2: fused dinv (blocks 0..78) + weight-fold (blocks 79..94) ------
// Fold: M = Wc@Wl[:C], b' = bc@Wl[:C] + bl.  The z-gate halves are additionally
// scaled by 0.5 so the gate can use (1-sigmoid(az)) = 0.5*(1 - tanh(az/2)).
#define DINV_BLOCKS 79
__global__ void k_dinv_precomp(const float* __restrict__ Wc_z, const float* __restrict__ bc_z,
                               const float* __restrict__ Wl_z, const float* __restrict__ bl_z,
                               const float* __restrict__ Wc_h, const float* __restrict__ bc_h,
                               const float* __restrict__ Wl_h, const float* __restrict__ bl_h,
                               const float* __restrict__ attention) {
    int tid = threadIdx.x;
    if (blockIdx.x < DINV_BLOCKS) {
        int i = blockIdx.x * 256 + tid;
        if (i < N_NODES) {
            float s = 0.f;
#pragma unroll
            for (int r = 0; r < NREG; r++) {
                float d = g_degacc[r * N_NODES + i] + 1.0f;   // +1 self-loop
                g_degacc[r * N_NODES + i] = 0.f;              // clean for next call
                g_dinv[r * N_NODES + i] = rsqrtf(d);
                s += __fdividef(1.0f, d);
            }
            g_selfc[i] = s;
        }
        return;
    }
    __shared__ float sWcz[F_DIM * 16], sWch[F_DIM * 16];
    __shared__ float sbcz[16], sbch[16];
    int b = blockIdx.x - DINV_BLOCKS;   // 0..15
    int k0 = b * 16;
    if (tid < F_DIM * 16) {
        int f = tid >> 4, kk = tid & 15;
        sWcz[tid] = Wc_z[f * C_DIM + k0 + kk];
        sWch[tid] = Wc_h[f * C_DIM + k0 + kk];
    }
    if (tid < 16) { sbcz[tid] = bc_z[k0 + tid]; sbch[tid] = bc_h[k0 + tid]; }
    __syncthreads();
    float mz[F_DIM] = {0, 0, 0, 0}, mh[F_DIM] = {0, 0, 0, 0}, bz = 0.f, bh = 0.f;
#pragma unroll 4
    for (int kk = 0; kk < 16; kk++) {
        int k = k0 + kk;
        float wz = Wl_z[k * C_DIM + tid];
        float wh = Wl_h[k * C_DIM + tid];
#pragma unroll
        for (int f = 0; f < F_DIM; f++) {
            mz[f] = fmaf(sWcz[f * 16 + kk], wz, mz[f]);
            mh[f] = fmaf(sWch[f * 16 + kk], wh, mh[f]);
        }
        bz = fmaf(sbcz[kk], wz, bz);
        bh = fmaf(sbch[kk], wh, bh);
    }
#pragma unroll
    for (int f = 0; f < F_DIM; f++) {
        atomicAdd(&g_Mzh[(f * C_DIM + tid) * 2],     0.5f * mz[f]);  // z-half carries the /2
        atomicAdd(&g_Mzh[(f * C_DIM + tid) * 2 + 1], mh[f]);
    }
    if (b == 0) { bz += bl_z[tid]; bh += bl_h[tid]; }
    atomicAdd(&g_bzh[tid * 2],     0.5f * bz);                        // z-half carries the /2
    atomicAdd(&g_bzh[tid * 2 + 1], bh);
    if (b == 0 && tid == 0) {
        float mx = -1e30f;
        for (int t = 0; t < T_DIM; t++) mx = fmaxf(mx, attention[t]);
        float p[T_DIM], s = 0.f;
        for (int t = 0; t < T_DIM; t++) { p[t] = __expf(attention[t] - mx); s += p[t]; }
        float is = __fdividef(0.5f, s);                               // 0.5 * softmax folded here
        for (int t = 0; t < T_DIM; t++) g_probs[t] = p[t] * is;
    }
}

// ---------------- 3: edge scatter with v4 reductions ----------------
// 4 lanes per edge; each lane does 3 x red.global.add.v4.f32 (48 floats/edge)
__global__ void k_scatter(RegPtrs rp) {
    int lane = threadIdx.x & 31;
    int warp = threadIdx.x >> 5;                       // 0..7
    int r = blockIdx.y;
    int e = (blockIdx.x * 8 + warp) * 8 + (lane >> 2);
    int part = lane & 3;
    if (e >= ER_E) return;
    const int* idx = rp.idx[r];
    int src = idx[e];
    int dst = idx[ER_E + e];
    float coef = g_dinv[r * N_NODES + src] * rp.w[r][e] * g_dinv[r * N_NODES + dst];
    const float4* xs = (const float4*)(g_Xp + (size_t)src * FT) + part * 3;
    float4* ax = (float4*)(g_AX + (size_t)dst * FT) + part * 3;
#pragma unroll
    for (int q = 0; q < 3; q++) {
        float4 v = xs[q];
        asm volatile("red.global.add.v4.f32 [%0], {%1, %2, %3, %4};"
                     :: "l"(ax + q), "f"(coef * v.x), "f"(coef * v.y),
                        "f"(coef * v.z), "f"(coef * v.w) : "memory");
    }
}

// ---------------- 4 (PROFILED SLOT): gate kernel, low-smem / high-occ ----------------
// h = sum_t (0.5*p_t) * (1 - tanh(az')) * tanh(ah),  az' = az/2 via weight fold
#define GATE_NPB 32

__global__ void __launch_bounds__(256, 6)
k_gate(float* __restrict__ out_h, int write_h) {
    __shared__ float AXs[GATE_NPB * FT];   // 1536 floats, [n][t*4+f]
    __shared__ float hs[8 * 260];          // 8-node transpose wave (pad 260: conflict-free)

    int tid = threadIdx.x;
    int base = blockIdx.x * GATE_NPB;

    // fused self-loop: AX_total = AX_edges + selfc[n] * Xp ; clean AX for next call
    for (int i = tid; i < GATE_NPB * FT; i += 256) {
        int n = base + i / FT;
        float v = fmaf(g_selfc[n], g_Xp[base * FT + i], g_AX[base * FT + i]);
        g_AX[base * FT + i] = 0.f;
        AXs[i] = v;
    }

    // per-channel folded weights straight from global (coalesced float2, L2-resident;
    // zero cross-thread reuse so smem staging would be pure overhead)
    int c = tid;
    float mz[F_DIM], mh[F_DIM];
    const float2* M2 = (const float2*)g_Mzh;
#pragma unroll
    for (int f = 0; f < F_DIM; f++) { float2 p = M2[f * C_DIM + c]; mz[f] = p.x; mh[f] = p.y; }
    float2 bp = ((const float2*)g_bzh)[c];
    float bz = bp.x, bh = bp.y;
    float pr2[T_DIM];
#pragma unroll
    for (int t = 0; t < T_DIM; t++) pr2[t] = g_probs[t];
    __syncthreads();

    for (int wave = 0; wave < 4; wave++) {
        if (wave) __syncthreads();         // hs reuse boundary
#pragma unroll 2
        for (int lw = 0; lw < 8; lw++) {
            int ln = wave * 8 + lw;
            const float4* ax4 = (const float4*)(AXs + ln * FT);
            float accA = 0.f, accB = 0.f;  // dual accumulators: halve the fma chain
#pragma unroll
            for (int t = 0; t < T_DIM; t++) {
                float4 a = ax4[t];         // broadcast LDS.128
                float az = fmaf(a.w, mz[3], fmaf(a.z, mz[2], fmaf(a.y, mz[1], fmaf(a.x, mz[0], bz))));
                float ah = fmaf(a.w, mh[3], fmaf(a.z, mh[2], fmaf(a.y, mh[1], fmaf(a.x, mh[0], bh))));
                float t1, t2;
                asm("tanh.approx.f32 %0, %1;" : "=f"(t1) : "f"(az));
                asm("tanh.approx.f32 %0, %1;" : "=f"(t2) : "f"(ah));
                float w = pr2[t] * (1.0f - t1);
                if (t & 1) accB = fmaf(w, t2, accB); else accA = fmaf(w, t2, accA);
            }
            float acc = accA + accB;
            if (write_h) out_h[(base + ln) * C_DIM + c] = acc;   // raw h output
            hs[lw * 260 + c] = fmaxf(acc, 0.f);
        }
        __syncthreads();
        // transposed relu'd dump for this 8-node wave: g_hreluT[c][n]
        for (int idx = tid; idx < 8 * C_DIM; idx += 256) {
            int n = idx & 7, cc = idx >> 3;
            g_hreluT[cc * N_NODES + base + wave * 8 + n] = hs[n * 260 + cc];
        }
    }
}

// ---------------- 5: MLP kernel: relu(h) @ W1 -> relu -> @ W2 ----------------
// smem floats: hTs 16384 (reused as y1s) | b1 128 | b2 16 | W2 1536 = 18064
#define MLP_NPB   64
#define MLP_SMEMF (16384 + 128 + 16 + 1536)
#define MLP_SMEMB (MLP_SMEMF * 4)

__global__ void __launch_bounds__(256, 3)
k_mlp(const float* __restrict__ W1, const float* __restrict__ b1,
      const float* __restrict__ W2, const float* __restrict__ b2,
      float* __restrict__ out_y) {
    extern __shared__ float sm[];
    float* hTs = sm;                  // 16384  [k][n]  (aliased to y1s after sync)
    float* b1s = hTs + 16384;         // 128
    float* b2s = b1s + 128;           // 16
    float* W2s = b2s + 16;            // 1536

    int tid = threadIdx.x;
    int base = blockIdx.x * MLP_NPB;

    // block 0 also cleans the folded-weight accumulators for the next call
    if (blockIdx.x == 0) {
        for (int i = tid; i < F_DIM * C_DIM * 2; i += 256) g_Mzh[i] = 0.f;
        g_bzh[tid] = 0.f;
        g_bzh[256 + tid] = 0.f;
    }

    for (int i = tid; i < 1536; i += 256) W2s[i] = W2[i];
    if (tid < HID_D) b1s[tid] = b1[tid];
    if (tid < 16) b2s[tid] = (tid < OUT_D) ? b2[tid] : 0.f;
    for (int i = tid; i < C_DIM * MLP_NPB; i += 256) {
        int k = i >> 6, n = i & 63;
        int gn = base + n;
        hTs[i] = (gn < N_NODES) ? g_hreluT[k * N_NODES + gn] : 0.f;
    }
    __syncthreads();

    // layer 1, packed-fp32 pipe: thread (j, half) covers 32 nodes = 16 f32x2 pairs
    int j = tid & 127;
    int half = tid >> 7;
    unsigned long long acc[16];
    {
        float bj = b1s[j];
        unsigned long long binit;
        asm("mov.b64 %0, {%1, %1};" : "=l"(binit) : "f"(bj));
#pragma unroll
        for (int p = 0; p < 16; p++) acc[p] = binit;
    }
    const float* hbase = hTs + half * 32;
#pragma unroll 1
    for (int k0 = 0; k0 < C_DIM; k0 += 8) {
        float wreg[8];                               // 8-wide prefetch
#pragma unroll
        for (int kk = 0; kk < 8; kk++) wreg[kk] = W1[(k0 + kk) * HID_D + j];
#pragma unroll
        for (int kk = 0; kk < 8; kk++) {
            unsigned long long w2;
            asm("mov.b64 %0, {%1, %1};" : "=l"(w2) : "f"(wreg[kk]));
            const ulonglong2* hp = (const ulonglong2*)(hbase + (k0 + kk) * MLP_NPB);
#pragma unroll
            for (int q = 0; q < 8; q++) {
                ulonglong2 hv = hp[q];
                asm("fma.rn.f32x2 %0, %1, %2, %0;" : "+l"(acc[2 * q])     : "l"(hv.x), "l"(w2));
                asm("fma.rn.f32x2 %0, %1, %2, %0;" : "+l"(acc[2 * q + 1]) : "l"(hv.y), "l"(w2));
            }
        }
    }
    __syncthreads();          // everyone done reading hTs
    float* y1s = hTs;         // reuse as [n][j]
#pragma unroll
    for (int p = 0; p < 16; p++) {
        float lo, hi;
        asm("mov.b64 {%0, %1}, %2;" : "=f"(lo), "=f"(hi) : "l"(acc[p]));
        int n0 = half * 32 + 2 * p;
        y1s[n0 * HID_D + j]       = fmaxf(lo, 0.f);
        y1s[(n0 + 1) * HID_D + j] = fmaxf(hi, 0.f);
    }
    __syncthreads();

    // layer 2: 64 nodes x 12 outputs
    for (int o = tid; o < MLP_NPB * OUT_D; o += 256) {
        int n = o / OUT_D, oo = o - n * OUT_D;
        int gn = base + n;
        if (gn < N_NODES) {
            float s = b2s[oo];
            const float* yr = y1s + n * HID_D;
#pragma unroll 16
            for (int jj = 0; jj < HID_D; jj++) s = fmaf(yr[jj], W2s[jj * OUT_D + oo], s);
            out_y[gn * OUT_D + oo] = s;
        }
    }
}

// ---------------- launch ----------------
extern "C" void kernel_launch(void* const* d_in, const int* in_sizes, int n_in,
                              void* d_out, int out_size) {
    (void)in_sizes; (void)n_in;
    const float* x = (const float*)d_in[0];
    // d_in[1] = full-graph edge_index: provably unused by the reference
    RegPtrs rp;
    for (int r = 0; r < NREG; r++) {
        rp.idx[r] = (const int*)d_in[2 + r];
        rp.w[r]   = (const float*)d_in[7 + r];
    }
    const float* Wc_z = (const float*)d_in[12];
    const float* bc_z = (const float*)d_in[13];
    const float* Wl_z = (const float*)d_in[14];
    const float* bl_z = (const float*)d_in[15];
    // d_in[16..19] = reset-gate params: cannot influence output (H0 = 0)
    const float* Wc_h = (const float*)d_in[20];
    const float* bc_h = (const float*)d_in[21];
    const float* Wl_h = (const float*)d_in[22];
    const float* bl_h = (const float*)d_in[23];
    const float* att  = (const float*)d_in[24];
    const float* W1   = (const float*)d_in[25];
    const float* b1   = (const float*)d_in[26];
    const float* W2   = (const float*)d_in[27];
    const float* b2   = (const float*)d_in[28];

    float* out   = (float*)d_out;
    float* out_y = out;
    int write_h  = (out_size >= N_NODES * (OUT_D + C_DIM)) ? 1 : 0;
    float* out_h = out + N_NODES * OUT_D;

    k_deg_perm<<<(N_NODES * FT + 255) / 256, 256>>>(x, rp);              // 1
    k_dinv_precomp<<<DINV_BLOCKS + 16, 256>>>(Wc_z, bc_z, Wl_z, bl_z,
                                              Wc_h, bc_h, Wl_h, bl_h, att); // 2
    dim3 gsc((ER_E + 63) / 64, NREG);   // 64 edges/block, 4 lanes/edge
    k_scatter<<<gsc, 256>>>(rp);                                         // 3

    k_gate<<<N_NODES / GATE_NPB, 256>>>(out_h, write_h);                 // 4 <- profiled

    cudaFuncSetAttribute(k_mlp, cudaFuncAttributeMaxDynamicSharedMemorySize, MLP_SMEMB);
    k_mlp<<<(N_NODES + MLP_NPB - 1) / MLP_NPB, 256, MLP_SMEMB>>>(W1, b1, W2, b2, out_y); // 5
}